// round 5
// baseline (speedup 1.0000x reference)
#include <cuda_runtime.h>
#include <cstdint>

// Problem constants (fixed shapes for this dataset)
#define SDIM 9
#define FDIM 32
#define MAXN 16384
#define MAXE 524288

// ---------------- scratch (no allocations allowed) ----------------
__device__ int g_count[MAXN];
__device__ int g_off[MAXN + 1];
__device__ int g_cursor[MAXN];
__device__ int g_srcs[MAXE];  // dst-sorted src indices (separate stream)
// dst-sorted edge records: 5 float4 per edge:
//   rec[0] = (unused, wr8, wa8, unused)
//   rec[1] = (wr0, wr1, wr2, wr3)      wr[r] = env(Y0) * Y[r]
//   rec[2] = (wr4, wr5, wr6, wr7)
//   rec[3] = (wa0, wa1, wa2, wa3)      wa[s] = env(dist) * Y[s]
//   rec[4] = (wa4, wa5, wa6, wa7)
__device__ float4 g_rec[(size_t)MAXE * 5];

// ---------------- helpers ----------------
__device__ __forceinline__ float envelope_f(float d) {
    float u = __saturatef(d);
    float u2 = u * u;
    float u5 = u2 * u2 * u;
    return 1.0f + u5 * (-21.0f + u * (35.0f - 15.0f * u));
}

__device__ __forceinline__ unsigned long long pack2(float lo, float hi) {
    unsigned long long r;
    asm("mov.b64 %0, {%1, %2};" : "=l"(r) : "f"(lo), "f"(hi));
    return r;
}
__device__ __forceinline__ void unpack2(unsigned long long v, float& lo, float& hi) {
    asm("mov.b64 {%0, %1}, %2;" : "=f"(lo), "=f"(hi) : "l"(v));
}
// d = a * b + d   (packed 2x f32, Blackwell)
__device__ __forceinline__ void ffma2(unsigned long long& d,
                                      unsigned long long a,
                                      unsigned long long b) {
    asm("fma.rn.f32x2 %0, %1, %2, %0;" : "+l"(d) : "l"(a), "l"(b));
}

// ---------------- CSR build ----------------
__global__ void zero_kernel(int Nn) {
    int i = blockIdx.x * blockDim.x + threadIdx.x;
    if (i < Nn) g_count[i] = 0;
}

__global__ void hist_kernel(const int* __restrict__ ei, int E) {
    int e = blockIdx.x * blockDim.x + threadIdx.x;
    if (e < E) atomicAdd(&g_count[ei[E + e]], 1);  // dst = edge_index[1][e]
}

// single block, 1024 threads, exclusive scan of g_count -> g_off, init g_cursor
__global__ void scan_kernel(int Nn, int E) {
    __shared__ int wsum[32];
    const int PER = 16;
    int t = threadIdx.x;
    int base = t * PER;
    int c[PER];
    int tsum = 0;
#pragma unroll
    for (int k = 0; k < PER; k++) {
        int v = (base + k < Nn) ? g_count[base + k] : 0;
        c[k] = v;
        tsum += v;
    }
    int lane = t & 31, w = t >> 5;
    int v = tsum;
#pragma unroll
    for (int d = 1; d < 32; d <<= 1) {
        int o = __shfl_up_sync(0xffffffffu, v, d);
        if (lane >= d) v += o;
    }
    if (lane == 31) wsum[w] = v;
    __syncthreads();
    if (w == 0) {
        int s = wsum[lane];
#pragma unroll
        for (int d = 1; d < 32; d <<= 1) {
            int o = __shfl_up_sync(0xffffffffu, s, d);
            if (lane >= d) s += o;
        }
        wsum[lane] = s;  // inclusive warp sums
    }
    __syncthreads();
    int excl = v - tsum + ((w > 0) ? wsum[w - 1] : 0);
    int run = excl;
#pragma unroll
    for (int k = 0; k < PER; k++) {
        if (base + k < Nn) {
            g_off[base + k] = run;
            g_cursor[base + k] = run;
            run += c[k];
        }
    }
    if (t == 0) g_off[Nn] = E;
}

// fused scatter + per-edge scalar precompute: writes dst-sorted records + src stream
__global__ void build_records(const int* __restrict__ ei,
                              const float* __restrict__ ea, int E) {
    int e = blockIdx.x * blockDim.x + threadIdx.x;
    if (e >= E) return;
    int src = ei[e];
    int dst = ei[E + e];

    const float2* p = (const float2*)(ea + (size_t)e * (SDIM * 2));
    float Y[SDIM];
    float dist;
    {
        float2 v0 = p[0];
        Y[0] = v0.x;
        dist = v0.y;
#pragma unroll
        for (int s = 1; s < SDIM; s++) Y[s] = p[s].x;
    }
    float env_d = envelope_f(dist);
    float env_y = envelope_f(Y[0]);

    int pos = atomicAdd(&g_cursor[dst], 1);
    g_srcs[pos] = src;
    float4* rec = g_rec + (size_t)pos * 5;
    rec[0] = make_float4(0.0f, env_y * Y[8], env_d * Y[8], 0.0f);
    rec[1] = make_float4(env_y * Y[0], env_y * Y[1], env_y * Y[2], env_y * Y[3]);
    rec[2] = make_float4(env_y * Y[4], env_y * Y[5], env_y * Y[6], env_y * Y[7]);
    rec[3] = make_float4(env_d * Y[0], env_d * Y[1], env_d * Y[2], env_d * Y[3]);
    rec[4] = make_float4(env_d * Y[4], env_d * Y[5], env_d * Y[6], env_d * Y[7]);
}

// ---------------- main aggregation: TWO warps per destination node ----------------
// Warp half h owns q range: h=0 -> q in [0,5), h=1 -> q in [5,9).
// lane = channel f. Per-warp accumulators (<=50 regs):
//   A[k]     = sum_e wa[Q0+k] * x[src,Q0+k,f]
//   Z[k][r]  = sum_e wr[r] * x[src,Q0+k,f]     (r packed in f32x2 pairs + r=8)
// Epilogue: each warp computes partial mixed[p] over its q slice for all 9 p,
// exchanges the other half's p-range via smem, then writes its own p-range.
template <int Q0, int NQ, int PO0, int PON>
__device__ __forceinline__ void node_accum(
    int beg, int end, int lane, int node_in_blk,
    const float* __restrict__ x, const float* cgs,
    float (&smem_part)[2][SDIM][32],
    float (&A)[5], float (&own)[5]) {
    unsigned long long Z2[NQ][4];
    float Z8[NQ];
#pragma unroll
    for (int k = 0; k < NQ; k++) {
#pragma unroll
        for (int rp = 0; rp < 4; rp++) Z2[k][rp] = 0ull;
        Z8[k] = 0.0f;
        A[k] = 0.0f;
    }

#pragma unroll 2
    for (int i = beg; i < end; ++i) {
        int src = __ldg(&g_srcs[i]);
        const float* xp = x + (size_t)src * (SDIM * FDIM) + lane;
        float xj[NQ];
#pragma unroll
        for (int k = 0; k < NQ; k++) xj[k] = __ldg(xp + (Q0 + k) * FDIM);

        const float4* rec = g_rec + (size_t)i * 5;
        float4 r0 = __ldg(rec + 0);
        float4 r1 = __ldg(rec + 1);
        float4 r2 = __ldg(rec + 2);

        unsigned long long wr2[4];
        wr2[0] = pack2(r1.x, r1.y);
        wr2[1] = pack2(r1.z, r1.w);
        wr2[2] = pack2(r2.x, r2.y);
        wr2[3] = pack2(r2.z, r2.w);
        float wr8 = r0.y;

        float wa[NQ];
        if (Q0 == 0) {
            float4 r3 = __ldg(rec + 3);
            float4 r4 = __ldg(rec + 4);
            wa[0] = r3.x; wa[1] = r3.y; wa[2] = r3.z; wa[3] = r3.w;
            if (NQ > 4) wa[4] = r4.x;
        } else {
            float4 r4 = __ldg(rec + 4);
            wa[0] = r4.y; wa[1] = r4.z; wa[2] = r4.w; wa[3] = r0.z;
        }

#pragma unroll
        for (int k = 0; k < NQ; k++) {
            unsigned long long xq2 = pack2(xj[k], xj[k]);
#pragma unroll
            for (int rp = 0; rp < 4; rp++) ffma2(Z2[k][rp], xq2, wr2[rp]);
            Z8[k] = fmaf(xj[k], wr8, Z8[k]);
            A[k] = fmaf(wa[k], xj[k], A[k]);
        }
    }

    // partial cg contraction over this warp's q slice, all 9 p
#pragma unroll
    for (int p = 0; p < SDIM; p++) {
        unsigned long long acc2 = 0ull;
        float accs = 0.0f;
#pragma unroll
        for (int k = 0; k < NQ; k++) {
            const float* cr = &cgs[p * 90 + (Q0 + k) * 10];
            const unsigned long long* cr2 = (const unsigned long long*)cr;
#pragma unroll
            for (int rp = 0; rp < 4; rp++) ffma2(acc2, cr2[rp], Z2[k][rp]);
            accs = fmaf(cr[8], Z8[k], accs);
        }
        float lo, hi;
        unpack2(acc2, lo, hi);
        float part = lo + hi + accs;
        if (p >= PO0 && p < PO0 + PON) {
            smem_part[node_in_blk][p][lane] = part;  // other half's output range
        } else {
            own[p - Q0] = part;  // our own output range
        }
    }
}

__global__ __launch_bounds__(128, 4) void aggregate_kernel(
    const float* __restrict__ x, const float* __restrict__ Wsca,
    const float* __restrict__ Wsph, const float* __restrict__ Wmix,
    const float* __restrict__ cg, float* __restrict__ out, int Nn) {
    __shared__ __align__(16) float cgs[SDIM * SDIM * 10];
    __shared__ float smem_part[2][SDIM][32];
    int tid = threadIdx.x;
    for (int i = tid; i < SDIM * SDIM * 10; i += blockDim.x) {
        int r = i % 10;
        int pq = i / 10;
        cgs[i] = (r < 9) ? cg[pq * 9 + r] : 0.0f;
    }
    __syncthreads();

    int warp = tid >> 5;
    int lane = tid & 31;
    int node_in_blk = warp >> 1;  // 0..1
    int h = warp & 1;
    int n = blockIdx.x * 2 + node_in_blk;
    bool valid = (n < Nn);
    int beg = valid ? g_off[n] : 0;
    int end = valid ? g_off[n + 1] : 0;

    float A[5], own[5];
    if (h == 0)
        node_accum<0, 5, 5, 4>(beg, end, lane, node_in_blk, x, cgs, smem_part, A, own);
    else
        node_accum<5, 4, 0, 5>(beg, end, lane, node_in_blk, x, cgs, smem_part, A, own);

    __syncthreads();

    if (valid) {
        int Q0 = h ? 5 : 0;
        int NQ = h ? 4 : 5;
#pragma unroll 5
        for (int k = 0; k < NQ; k++) {
            int p = Q0 + k;
            float mixed = own[k] + smem_part[node_in_blk][p][lane];
            int lp = (p == 0) ? 0 : ((p < 4) ? 1 : 2);
            float wa_ = Wsca[lp * FDIM + lane] * Wsph[lp * FDIM + lane];
            float wm = Wmix[lp * FDIM + lane];
            size_t o = (size_t)n * (SDIM * FDIM) + p * FDIM + lane;
            out[o] = x[o] + wa_ * A[k] + wm * mixed;
        }
    }
}

// ---------------- launch ----------------
extern "C" void kernel_launch(void* const* d_in, const int* in_sizes, int n_in,
                              void* d_out, int out_size) {
    const float* x    = (const float*)d_in[0];
    const int*   ei   = (const int*)d_in[1];
    const float* ea   = (const float*)d_in[2];
    const float* Wsca = (const float*)d_in[3];
    const float* Wsph = (const float*)d_in[4];
    const float* Wmix = (const float*)d_in[5];
    const float* cg   = (const float*)d_in[6];
    float* out = (float*)d_out;

    int E  = in_sizes[1] / 2;
    int Nn = in_sizes[0] / (SDIM * FDIM);

    zero_kernel<<<(Nn + 255) / 256, 256>>>(Nn);
    hist_kernel<<<(E + 255) / 256, 256>>>(ei, E);
    scan_kernel<<<1, 1024>>>(Nn, E);
    build_records<<<(E + 255) / 256, 256>>>(ei, ea, E);

    // two warps per node, 128 threads = 2 nodes per block
    int blocks = (Nn + 1) / 2;
    aggregate_kernel<<<blocks, 128>>>(x, Wsca, Wsph, Wmix, cg, out, Nn);
}